// round 1
// baseline (speedup 1.0000x reference)
#include <cuda_runtime.h>
#include <cuda_bf16.h>
#include <cooperative_groups.h>
#include <cstdint>

namespace cg = cooperative_groups;

// Problem constants
#define Bsz 32
#define Tlen 1024
#define Idim 512
#define Hdim 512

// Scratch for the input projection (device global: no allocation allowed)
__device__ float g_xproj[(size_t)Bsz * Tlen * Hdim];  // 64 MB

// ---------------------------------------------------------------------------
// Kernel 1: xproj[m, h] = sum_i X[m, i] * Wih[h, i] + bih[h] + bhh[h]
//   M = B*T = 32768, N = H = 512, K = I = 512, fp32 SGEMM 128x128x16, 8x8 micro
// ---------------------------------------------------------------------------
__global__ void __launch_bounds__(256) xproj_kernel(
    const float* __restrict__ X,     // [32768, 512]
    const float* __restrict__ Wih,   // [512, 512]
    const float* __restrict__ bih,
    const float* __restrict__ bhh)
{
    const int BM = 128, BN = 128, BK = 16;
    __shared__ __align__(16) float As[BK][BM + 4];
    __shared__ __align__(16) float Bs[BK][BN + 4];

    const int tid = threadIdx.x;
    const int m0 = blockIdx.y * BM;
    const int n0 = blockIdx.x * BN;
    const int tx = tid & 15;        // n micro-tile
    const int ty = tid >> 4;        // m micro-tile

    float acc[8][8];
#pragma unroll
    for (int i = 0; i < 8; ++i)
#pragma unroll
        for (int j = 0; j < 8; ++j) acc[i][j] = 0.f;

    for (int k0 = 0; k0 < Idim; k0 += BK) {
        // Load A tile (128x16) and B tile (128x16), k-major in smem
#pragma unroll
        for (int q = 0; q < 2; ++q) {
            int lin = tid + 256 * q;          // 0..511
            int m = lin >> 2;                 // 0..127
            int kv = (lin & 3) << 2;          // 0,4,8,12
            float4 va = *(const float4*)(X + (size_t)(m0 + m) * Idim + k0 + kv);
            As[kv + 0][m] = va.x; As[kv + 1][m] = va.y;
            As[kv + 2][m] = va.z; As[kv + 3][m] = va.w;
            float4 vb = *(const float4*)(Wih + (size_t)(n0 + m) * Idim + k0 + kv);
            Bs[kv + 0][m] = vb.x; Bs[kv + 1][m] = vb.y;
            Bs[kv + 2][m] = vb.z; Bs[kv + 3][m] = vb.w;
        }
        __syncthreads();

#pragma unroll
        for (int kk = 0; kk < BK; ++kk) {
            float ra[8], rb[8];
            *(float4*)&ra[0] = *(const float4*)&As[kk][ty * 8];
            *(float4*)&ra[4] = *(const float4*)&As[kk][ty * 8 + 4];
            *(float4*)&rb[0] = *(const float4*)&Bs[kk][tx * 8];
            *(float4*)&rb[4] = *(const float4*)&Bs[kk][tx * 8 + 4];
#pragma unroll
            for (int i = 0; i < 8; ++i)
#pragma unroll
                for (int j = 0; j < 8; ++j)
                    acc[i][j] = fmaf(ra[i], rb[j], acc[i][j]);
        }
        __syncthreads();
    }

    // Epilogue: add (bih + bhh), store
    float bsum[8];
#pragma unroll
    for (int j = 0; j < 8; ++j)
        bsum[j] = bih[n0 + tx * 8 + j] + bhh[n0 + tx * 8 + j];

#pragma unroll
    for (int i = 0; i < 8; ++i) {
        float4 o0 = make_float4(acc[i][0] + bsum[0], acc[i][1] + bsum[1],
                                acc[i][2] + bsum[2], acc[i][3] + bsum[3]);
        float4 o1 = make_float4(acc[i][4] + bsum[4], acc[i][5] + bsum[5],
                                acc[i][6] + bsum[6], acc[i][7] + bsum[7]);
        float* crow = g_xproj + (size_t)(m0 + ty * 8 + i) * Hdim + n0 + tx * 8;
        *(float4*)(crow) = o0;
        *(float4*)(crow + 4) = o1;
    }
}

// ---------------------------------------------------------------------------
// Kernel 2: the recurrence.
//   Grid: (8 H-slices) x (16 batch-groups).  Cluster = 8 CTAs (one batch-group).
//   CTA: 256 threads, 2 batches, 64 outputs, K=512.
//   Whh slice lives in REGISTERS (128 floats/thread) for all 1024 steps.
//   History ring hist[8][2][512] in SMEM, replicated per CTA; each step the
//   new h slice is multicast to all 8 cluster CTAs via DSMEM, then cluster.sync.
// ---------------------------------------------------------------------------
__global__ void __launch_bounds__(256, 1) __cluster_dims__(8, 1, 1)
rnn_kernel(const float* __restrict__ Whh,   // [512, 512]
           const float* __restrict__ kern,  // [4]
           float* __restrict__ out_states,  // [B, T, H]
           float* __restrict__ out_last)    // [B, H]
{
    __shared__ float hist[8][2][Hdim];               // 32 KB history ring
    __shared__ __align__(16) float hr[2][Hdim];      // interpolated read

    cg::cluster_group cluster = cg::this_cluster();

    const int tid   = threadIdx.x;
    const int slice = blockIdx.x;          // 0..7 == cluster rank
    const int grp   = blockIdx.y;          // 0..15
    const int b0    = grp * 2;
    const int b1    = b0 + 1;
    const int jl    = tid >> 2;            // 0..63 output within slice
    const int split = tid & 3;             // K-split 0..3
    const int jg    = slice * 64 + jl;     // global output index
    const int i0    = split * 128;         // K range start

    // Pin this thread's Whh slice in registers
    float w[128];
    {
        const float* wrow = Whh + (size_t)jg * Hdim + i0;
#pragma unroll
        for (int c = 0; c < 128; c += 4) {
            float4 v = *(const float4*)(wrow + c);
            w[c] = v.x; w[c + 1] = v.y; w[c + 2] = v.z; w[c + 3] = v.w;
        }
    }
    const float k0c = kern[0], k1c = kern[1], k2c = kern[2], k3c = kern[3];

    // Zero history (prev0 = 0)
    for (int idx = tid; idx < 8 * 2 * Hdim; idx += 256)
        ((float*)hist)[idx] = 0.f;
    cluster.sync();   // everyone zeroed before any peer writes arrive

    const float* xpr0 = g_xproj + (size_t)b0 * Tlen * Hdim + jg;
    const float* xpr1 = g_xproj + (size_t)b1 * Tlen * Hdim + jg;
    float* os0 = out_states + (size_t)b0 * Tlen * Hdim + jg;
    float* os1 = out_states + (size_t)b1 * Tlen * Hdim + jg;

    for (int t = 0; t < Tlen; ++t) {
        // Prefetch xproj for this step (holders only)
        float xv0 = 0.f, xv1 = 0.f;
        if (split == 0) {
            xv0 = __ldg(xpr0 + (size_t)t * Hdim);
            xv1 = __ldg(xpr1 + (size_t)t * Hdim);
        }

        // Lagrange-interpolated history read: hr = sum_k kern[k] * h_{t-1-k}
        const int s0 = (t - 1) & 7, s1 = (t - 2) & 7, s2 = (t - 3) & 7, s3 = (t - 4) & 7;
#pragma unroll
        for (int u = 0; u < 4; ++u) {
            int n  = tid + 256 * u;     // 0..1023
            int bb = n >> 9;
            int ii = n & (Hdim - 1);
            float v = k0c * hist[s0][bb][ii] + k1c * hist[s1][bb][ii]
                    + k2c * hist[s2][bb][ii] + k3c * hist[s3][bb][ii];
            hr[bb][ii] = v;
        }
        __syncthreads();

        // Register-resident GEMM slice: acc_b = sum_{i in split range} w[i]*hr[b][i]
        float a0 = 0.f, a0b = 0.f, a1 = 0.f, a1b = 0.f;
#pragma unroll
        for (int c = 0; c < 128; c += 4) {
            float4 h0 = *(const float4*)&hr[0][i0 + c];
            float4 h1 = *(const float4*)&hr[1][i0 + c];
            a0  = fmaf(w[c],     h0.x, a0);
            a0b = fmaf(w[c + 1], h0.y, a0b);
            a0  = fmaf(w[c + 2], h0.z, a0);
            a0b = fmaf(w[c + 3], h0.w, a0b);
            a1  = fmaf(w[c],     h1.x, a1);
            a1b = fmaf(w[c + 1], h1.y, a1b);
            a1  = fmaf(w[c + 2], h1.z, a1);
            a1b = fmaf(w[c + 3], h1.w, a1b);
        }
        float r0 = a0 + a0b;
        float r1 = a1 + a1b;

        // Reduce across the 4 K-splits (lanes 4j..4j+3 adjacent)
        r0 += __shfl_down_sync(0xFFFFFFFFu, r0, 2);
        r0 += __shfl_down_sync(0xFFFFFFFFu, r0, 1);
        r1 += __shfl_down_sync(0xFFFFFFFFu, r1, 2);
        r1 += __shfl_down_sync(0xFFFFFFFFu, r1, 1);

        if (split == 0) {
            float h0v = tanhf(r0 + xv0);   // xv already includes bih + bhh
            float h1v = tanhf(r1 + xv1);
            os0[(size_t)t * Hdim] = h0v;
            os1[(size_t)t * Hdim] = h1v;
            if (t == Tlen - 1) {
                out_last[(size_t)b0 * Hdim + jg] = h0v;
                out_last[(size_t)b1 * Hdim + jg] = h1v;
            }
            // Multicast the new h values into every cluster CTA's history ring
            const int slot = t & 7;
            float* l0 = &hist[slot][0][jg];
            float* l1 = &hist[slot][1][jg];
#pragma unroll
            for (int p = 0; p < 8; ++p) {
                float* r0p = cluster.map_shared_rank(l0, p);
                float* r1p = cluster.map_shared_rank(l1, p);
                *r0p = h0v;
                *r1p = h1v;
            }
        }
        cluster.sync();   // release stores / acquire for next step's hread
    }
}

// ---------------------------------------------------------------------------
extern "C" void kernel_launch(void* const* d_in, const int* in_sizes, int n_in,
                              void* d_out, int out_size)
{
    (void)in_sizes; (void)n_in; (void)out_size;
    const float* x    = (const float*)d_in[0];   // [32, 1024, 512]
    const float* Wih  = (const float*)d_in[1];   // [512, 512]
    const float* Whh  = (const float*)d_in[2];   // [512, 512]
    const float* bih  = (const float*)d_in[3];   // [512]
    const float* bhh  = (const float*)d_in[4];   // [512]
    const float* kern = (const float*)d_in[5];   // [4]

    float* out        = (float*)d_out;
    float* out_states = out;                                   // [32,1024,512]
    float* out_last   = out + (size_t)Bsz * Tlen * Hdim;       // [32,512]

    // 1) Input projection GEMM (+bih+bhh folded in)
    dim3 gg(Hdim / 128, (Bsz * Tlen) / 128);   // (4, 256)
    xproj_kernel<<<gg, 256>>>(x, Wih, bih, bhh);

    // 2) Sequential recurrence: 16 clusters of 8 CTAs
    dim3 gr(8, 16);
    rnn_kernel<<<gr, 256>>>(Whh, kern, out_states, out_last);
}

// round 2
// speedup vs baseline: 2.5255x; 2.5255x over previous
#include <cuda_runtime.h>
#include <cuda_bf16.h>
#include <cooperative_groups.h>
#include <cstdint>

namespace cg = cooperative_groups;

// Problem constants
#define Bsz 32
#define Tlen 1024
#define Idim 512
#define Hdim 512

// Scratch for the input projection (device global: no allocation allowed)
__device__ float g_xproj[(size_t)Bsz * Tlen * Hdim];  // 64 MB

// ---------------------------------------------------------------------------
// Kernel 1: xproj[m, h] = sum_i X[m, i] * Wih[h, i] + bih[h] + bhh[h]
//   M = B*T = 32768, N = H = 512, K = I = 512, fp32 SGEMM 128x128x16, 8x8 micro
// ---------------------------------------------------------------------------
__global__ void __launch_bounds__(256) xproj_kernel(
    const float* __restrict__ X,     // [32768, 512]
    const float* __restrict__ Wih,   // [512, 512]
    const float* __restrict__ bih,
    const float* __restrict__ bhh)
{
    const int BM = 128, BN = 128, BK = 16;
    __shared__ __align__(16) float As[BK][BM + 4];
    __shared__ __align__(16) float Bs[BK][BN + 4];

    const int tid = threadIdx.x;
    const int m0 = blockIdx.y * BM;
    const int n0 = blockIdx.x * BN;
    const int tx = tid & 15;        // n micro-tile
    const int ty = tid >> 4;        // m micro-tile

    float acc[8][8];
#pragma unroll
    for (int i = 0; i < 8; ++i)
#pragma unroll
        for (int j = 0; j < 8; ++j) acc[i][j] = 0.f;

    for (int k0 = 0; k0 < Idim; k0 += BK) {
#pragma unroll
        for (int q = 0; q < 2; ++q) {
            int lin = tid + 256 * q;          // 0..511
            int m = lin >> 2;                 // 0..127
            int kv = (lin & 3) << 2;          // 0,4,8,12
            float4 va = *(const float4*)(X + (size_t)(m0 + m) * Idim + k0 + kv);
            As[kv + 0][m] = va.x; As[kv + 1][m] = va.y;
            As[kv + 2][m] = va.z; As[kv + 3][m] = va.w;
            float4 vb = *(const float4*)(Wih + (size_t)(n0 + m) * Idim + k0 + kv);
            Bs[kv + 0][m] = vb.x; Bs[kv + 1][m] = vb.y;
            Bs[kv + 2][m] = vb.z; Bs[kv + 3][m] = vb.w;
        }
        __syncthreads();

#pragma unroll
        for (int kk = 0; kk < BK; ++kk) {
            float ra[8], rb[8];
            *(float4*)&ra[0] = *(const float4*)&As[kk][ty * 8];
            *(float4*)&ra[4] = *(const float4*)&As[kk][ty * 8 + 4];
            *(float4*)&rb[0] = *(const float4*)&Bs[kk][tx * 8];
            *(float4*)&rb[4] = *(const float4*)&Bs[kk][tx * 8 + 4];
#pragma unroll
            for (int i = 0; i < 8; ++i)
#pragma unroll
                for (int j = 0; j < 8; ++j)
                    acc[i][j] = fmaf(ra[i], rb[j], acc[i][j]);
        }
        __syncthreads();
    }

    float bsum[8];
#pragma unroll
    for (int j = 0; j < 8; ++j)
        bsum[j] = bih[n0 + tx * 8 + j] + bhh[n0 + tx * 8 + j];

#pragma unroll
    for (int i = 0; i < 8; ++i) {
        float4 o0 = make_float4(acc[i][0] + bsum[0], acc[i][1] + bsum[1],
                                acc[i][2] + bsum[2], acc[i][3] + bsum[3]);
        float4 o1 = make_float4(acc[i][4] + bsum[4], acc[i][5] + bsum[5],
                                acc[i][6] + bsum[6], acc[i][7] + bsum[7]);
        float* crow = g_xproj + (size_t)(m0 + ty * 8 + i) * Hdim + n0 + tx * 8;
        *(float4*)(crow) = o0;
        *(float4*)(crow + 4) = o1;
    }
}

// ---------------------------------------------------------------------------
// Kernel 2: the recurrence.
//   Grid: (8 H-slices) x (16 batch-groups).  Cluster = 8 CTAs (one batch-group).
//   CTA: 256 threads, 2 batches (packed as float2), 64 outputs, K = 512.
//   Thread (jl = tid>>2, split = tid&3) owns K chunks i = split*4 + 16*m,
//   so a warp's 4 splits hit ADJACENT 16B smem chunks (conflict-free) and the
//   8 jl-groups broadcast. Whh slice pinned in registers (32 float4/thread).
//   History ring hist[8][512][2] (batch-packed float2) in SMEM, replicated per
//   CTA; new h multicast to all 8 cluster CTAs via DSMEM float2 stores.
// ---------------------------------------------------------------------------
__global__ void __launch_bounds__(256, 1) __cluster_dims__(8, 1, 1)
rnn_kernel(const float* __restrict__ Whh,   // [512, 512]
           const float* __restrict__ kern,  // [4]
           float* __restrict__ out_states,  // [B, T, H]
           float* __restrict__ out_last)    // [B, H]
{
    __shared__ __align__(16) float hist[8][Hdim][2];   // 32 KB history ring
    __shared__ __align__(16) float hr[Hdim][2];        // interpolated read

    cg::cluster_group cluster = cg::this_cluster();

    const int tid   = threadIdx.x;
    const int slice = blockIdx.x;          // 0..7 == cluster rank
    const int grp   = blockIdx.y;          // 0..15
    const int b0    = grp * 2;
    const int b1    = b0 + 1;
    const int jl    = tid >> 2;            // 0..63 output within slice
    const int split = tid & 3;             // interleaved K-split 0..3
    const int jg    = slice * 64 + jl;     // global output index

    // Pin this thread's Whh slice in registers: chunks i = split*4 + 16*m
    float4 w4[32];
    {
        const float* wrow = Whh + (size_t)jg * Hdim + split * 4;
#pragma unroll
        for (int m = 0; m < 32; ++m)
            w4[m] = *(const float4*)(wrow + 16 * m);
    }
    const float k0c = kern[0], k1c = kern[1], k2c = kern[2], k3c = kern[3];

    // Zero history (prev0 = 0)
    for (int idx = tid; idx < 8 * Hdim * 2; idx += 256)
        ((float*)hist)[idx] = 0.f;
    cluster.sync();   // everyone zeroed before any peer writes arrive

    const float* xpr0 = g_xproj + (size_t)b0 * Tlen * Hdim + jg;
    const float* xpr1 = g_xproj + (size_t)b1 * Tlen * Hdim + jg;
    float* os0 = out_states + (size_t)b0 * Tlen * Hdim + jg;
    float* os1 = out_states + (size_t)b1 * Tlen * Hdim + jg;

    for (int t = 0; t < Tlen; ++t) {
        // Prefetch xproj for this step (holders only) — overlaps with hr work
        float xv0 = 0.f, xv1 = 0.f;
        if (split == 0) {
            xv0 = __ldg(xpr0 + (size_t)t * Hdim);
            xv1 = __ldg(xpr1 + (size_t)t * Hdim);
        }

        // Lagrange-interpolated history read: hr = sum_k kern[k] * h_{t-1-k}
        // float2 per element, consecutive threads -> consecutive addresses.
        const int s0 = (t - 1) & 7, s1 = (t - 2) & 7, s2 = (t - 3) & 7, s3 = (t - 4) & 7;
#pragma unroll
        for (int u = 0; u < 2; ++u) {
            int ii = tid + 256 * u;         // 0..511
            float2 v0 = *(const float2*)&hist[s0][ii][0];
            float2 v1 = *(const float2*)&hist[s1][ii][0];
            float2 v2 = *(const float2*)&hist[s2][ii][0];
            float2 v3 = *(const float2*)&hist[s3][ii][0];
            float2 r;
            r.x = k0c * v0.x + k1c * v1.x + k2c * v2.x + k3c * v3.x;
            r.y = k0c * v0.y + k1c * v1.y + k2c * v2.y + k3c * v3.y;
            *(float2*)&hr[ii][0] = r;
        }
        __syncthreads();

        // Register-resident GEMM slice over interleaved K chunks.
        // Each float4 load covers hr[i..i+1][0..1] (2 K-values x 2 batches).
        float a0 = 0.f, a1 = 0.f, c0 = 0.f, c1 = 0.f;
        const float4* hrp = (const float4*)&hr[split * 4][0];  // chunk base
#pragma unroll
        for (int m = 0; m < 32; ++m) {
            float4 hA = hrp[8 * m + 0];   // hr[i+0], hr[i+1]
            float4 hB = hrp[8 * m + 1];   // hr[i+2], hr[i+3]
            float4 w = w4[m];
            a0 = fmaf(w.x, hA.x, a0);
            a1 = fmaf(w.x, hA.y, a1);
            c0 = fmaf(w.y, hA.z, c0);
            c1 = fmaf(w.y, hA.w, c1);
            a0 = fmaf(w.z, hB.x, a0);
            a1 = fmaf(w.z, hB.y, a1);
            c0 = fmaf(w.w, hB.z, c0);
            c1 = fmaf(w.w, hB.w, c1);
        }
        float r0 = a0 + c0;
        float r1 = a1 + c1;

        // Reduce across the 4 K-splits (lanes 4j..4j+3 adjacent)
        r0 += __shfl_down_sync(0xFFFFFFFFu, r0, 2);
        r0 += __shfl_down_sync(0xFFFFFFFFu, r0, 1);
        r1 += __shfl_down_sync(0xFFFFFFFFu, r1, 2);
        r1 += __shfl_down_sync(0xFFFFFFFFu, r1, 1);

        if (split == 0) {
            float h0v = tanhf(r0 + xv0);   // xv already includes bih + bhh
            float h1v = tanhf(r1 + xv1);
            os0[(size_t)t * Hdim] = h0v;
            os1[(size_t)t * Hdim] = h1v;
            if (t == Tlen - 1) {
                out_last[(size_t)b0 * Hdim + jg] = h0v;
                out_last[(size_t)b1 * Hdim + jg] = h1v;
            }
            // Multicast the new h pair into every cluster CTA's history ring
            const int slot = t & 7;
            float2 hv = make_float2(h0v, h1v);
            float2* lp = (float2*)&hist[slot][jg][0];
#pragma unroll
            for (int p = 0; p < 8; ++p) {
                float2* rp = cluster.map_shared_rank(lp, p);
                *rp = hv;
            }
        }
        cluster.sync();   // release stores / acquire for next step's hread
    }
}

// ---------------------------------------------------------------------------
extern "C" void kernel_launch(void* const* d_in, const int* in_sizes, int n_in,
                              void* d_out, int out_size)
{
    (void)in_sizes; (void)n_in; (void)out_size;
    const float* x    = (const float*)d_in[0];   // [32, 1024, 512]
    const float* Wih  = (const float*)d_in[1];   // [512, 512]
    const float* Whh  = (const float*)d_in[2];   // [512, 512]
    const float* bih  = (const float*)d_in[3];   // [512]
    const float* bhh  = (const float*)d_in[4];   // [512]
    const float* kern = (const float*)d_in[5];   // [4]

    float* out        = (float*)d_out;
    float* out_states = out;                                   // [32,1024,512]
    float* out_last   = out + (size_t)Bsz * Tlen * Hdim;       // [32,512]

    // 1) Input projection GEMM (+bih+bhh folded in)
    dim3 gg(Hdim / 128, (Bsz * Tlen) / 128);   // (4, 256)
    xproj_kernel<<<gg, 256>>>(x, Wih, bih, bhh);

    // 2) Sequential recurrence: 16 clusters of 8 CTAs
    dim3 gr(8, 16);
    rnn_kernel<<<gr, 256>>>(Whh, kern, out_states, out_last);
}